// round 8
// baseline (speedup 1.0000x reference)
#include <cuda_runtime.h>
#include <cuda_bf16.h>
#include <cuda_fp16.h>
#include <math_constants.h>

#define NROW 32768
#define CDIM 256
#define NE   1024
#define MARGIN 8e-3f
#define RCAP 64

// ---- static device scratch (allocation-free rule) ----
__device__ float          g_zrm[(size_t)NROW * CDIM];   // z row-major [n][c] fp32 (written by gemm)
__device__ __nv_bfloat16  g_ebf[(size_t)NE * CDIM];     // bf16(emb) [j][k]
__device__ float          g_se[NE];
__device__ float          g_amin[NROW];                 // final per-row approx min (fp32)
__device__ __half         g_t[(size_t)NROW * NE];       // approx scores [row][code] fp16
__device__ double         g_partial[4096];

// ================= PTX helpers (baseline sm_80 ISA only) =================
__device__ __forceinline__ unsigned smem_u32(const void* p) {
    unsigned a;
    asm("{ .reg .u64 t; cvta.to.shared.u64 t, %1; cvt.u32.u64 %0, t; }" : "=r"(a) : "l"(p));
    return a;
}
__device__ __forceinline__ void cp16(unsigned dst, const void* src) {
    asm volatile("cp.async.cg.shared.global [%0], [%1], 16;" :: "r"(dst), "l"(src));
}
#define CP_COMMIT() asm volatile("cp.async.commit_group;" ::: "memory")
#define CP_WAIT(n)  asm volatile("cp.async.wait_group %0;" :: "n"(n) : "memory")

__device__ __forceinline__ void ldsm4(unsigned& r0, unsigned& r1, unsigned& r2, unsigned& r3,
                                      unsigned addr) {
    asm volatile("ldmatrix.sync.aligned.m8n8.x4.shared.b16 {%0,%1,%2,%3}, [%4];"
        : "=r"(r0), "=r"(r1), "=r"(r2), "=r"(r3) : "r"(addr));
}
__device__ __forceinline__ void mma16816(float* c, const unsigned* a, unsigned b0, unsigned b1) {
    asm volatile("mma.sync.aligned.m16n8k16.row.col.f32.bf16.bf16.f32 "
        "{%0,%1,%2,%3}, {%4,%5,%6,%7}, {%8,%9}, {%0,%1,%2,%3};"
        : "+f"(c[0]), "+f"(c[1]), "+f"(c[2]), "+f"(c[3])
        : "r"(a[0]), "r"(a[1]), "r"(a[2]), "r"(a[3]), "r"(b0), "r"(b1));
}
__device__ __forceinline__ unsigned fmapu(float f) {
    unsigned b = __float_as_uint(f);
    return (b & 0x80000000u) ? ~b : (b | 0x80000000u);
}
__device__ __forceinline__ float funmapu(unsigned u) {
    return (u & 0x80000000u) ? __uint_as_float(u & 0x7fffffffu) : __uint_as_float(~u);
}

// ================= prep kernels =================
__global__ void eprep_kernel(const float* __restrict__ e) {
    int i = blockIdx.x * 256 + threadIdx.x;
    g_ebf[i] = __float2bfloat16(e[i]);
}

// per-code norms (verbatim R1 rounding — known-passing)
__global__ void se_kernel(const float* __restrict__ e) {
    int j = blockIdx.x;
    float4 v = *(const float4*)&e[j * 256 + threadIdx.x * 4];
    float s = __fadd_rn(__fadd_rn(__fmul_rn(v.x,v.x), __fmul_rn(v.y,v.y)),
                        __fadd_rn(__fmul_rn(v.z,v.z), __fmul_rn(v.w,v.w)));
    for (int off = 16; off; off >>= 1) s += __shfl_down_sync(0xffffffffu, s, off);
    __shared__ float r2[2];
    if ((threadIdx.x & 31) == 0) r2[threadIdx.x >> 5] = s;
    __syncthreads();
    if (threadIdx.x == 0) g_se[j] = __fadd_rn(r2[0], r2[1]);
}

__global__ void pinit_kernel() {   // spacer (keeps gemm in profiled slot) + deterministic init
    g_partial[blockIdx.x * 256 + threadIdx.x] = 0.0;
}

// ================= single-pass HMMA scoring: score store + online final min =================
// smem: se 4KB | A 64KB | B 2x64KB (stage reuse) | min 512B
#define SE_OFF   0
#define A_OFF    4096
#define B_OFF    (4096 + 65536)
#define MIN_OFF  (B_OFF + 131072)          // 200704
#define SMEM_T   (MIN_OFF + 512)           // 201216

__global__ void __launch_bounds__(512) gemm_kernel(const float* __restrict__ z) {
    extern __shared__ char sm[];
    unsigned smb = smem_u32(sm);
    const int tid = threadIdx.x, l = tid & 31, w = tid >> 5;
    const int wm = w & 3, wn = w >> 2;           // 4x4 warp grid, 32x32 tiles
    const int row0 = blockIdx.x * 128;
    float* se_sm = (float*)(sm + SE_OFF);
    unsigned* sm_min = (unsigned*)(sm + MIN_OFF);

    if (tid < 256) ((float4*)se_sm)[tid] = ((const float4*)g_se)[tid];
    if (tid < 128) sm_min[tid] = 0xFFFFFFFFu;

    // ---- phase 1: load z slice from ORIGINAL layout, transpose via staging;
    //      emit fp32 zrm tile (for rescore) + bf16 A tile (swizzled) ----
    {
        const int b = row0 >> 10, hw0 = row0 & 1023;
        float* stg = (float*)(sm + B_OFF) + w * (36 * 32);   // 4608B per warp
        #pragma unroll
        for (int tt = 0; tt < 2; tt++) {
            int ti = w * 2 + tt;            // 32 tiles: ci 0..7 (c), hi 0..3 (hw)
            int ci = ti >> 2, hi = ti & 3;
            #pragma unroll
            for (int i = 0; i < 8; i++) {
                int cl = i * 4 + (l >> 3);
                float4 v = *(const float4*)&z[((size_t)b << 18) + (size_t)(ci * 32 + cl) * 1024
                                              + hw0 + hi * 32 + (l & 7) * 4];
                *(float4*)&stg[cl * 36 + (l & 7) * 4] = v;
            }
            __syncwarp();
            int c = ci * 32 + l;
            #pragma unroll
            for (int rr = 0; rr < 32; rr++) {
                float v = stg[l * 36 + rr];
                int r = hi * 32 + rr;
                g_zrm[(size_t)(row0 + r) * 256 + c] = v;
                *(__nv_bfloat16*)(sm + A_OFF + r * 512 + ((c * 2) ^ ((r & 7) << 4))) =
                    __float2bfloat16(v);
            }
            __syncwarp();
        }
    }
    __syncthreads();   // A ready; staging region free for B

    // ---- B chunk 0 via cp.async ----
    const char* esrc = (const char*)g_ebf;
    #pragma unroll
    for (int i = 0; i < 8; i++) {
        int f = tid + i * 512, r = f >> 5, kb16 = f & 31;
        cp16(smb + B_OFF + r * 512 + ((kb16 * 16) ^ ((r & 7) << 4)),
             esrc + (size_t)r * 512 + kb16 * 16);
    }
    CP_COMMIT();

    const unsigned c16 = ((l >> 4) & 1) * 16;
    unsigned aBase[2], xA[2];
    #pragma unroll
    for (int mf = 0; mf < 2; mf++) {
        int r = wm * 32 + mf * 16 + (l & 15);
        aBase[mf] = smb + A_OFF + r * 512;
        xA[mf] = c16 ^ ((r & 7) << 4);
    }
    unsigned bRow[2], xB[2];
    #pragma unroll
    for (int nfp = 0; nfp < 2; nfp++) {
        int r = wn * 32 + nfp * 16 + ((l >> 3) & 1) * 8 + (l & 7);
        bRow[nfp] = r * 512;
        xB[nfp] = c16 ^ ((r & 7) << 4);
    }

    for (int t = 0; t < 8; t++) {
        if (t < 7) {
            const char* src = esrc + (size_t)(t + 1) * 128 * 512;
            unsigned dstb = smb + B_OFF + ((t + 1) & 1) * 65536;
            #pragma unroll
            for (int i = 0; i < 8; i++) {
                int f = tid + i * 512, r = f >> 5, kb16 = f & 31;
                cp16(dstb + r * 512 + ((kb16 * 16) ^ ((r & 7) << 4)),
                     src + (size_t)r * 512 + kb16 * 16);
            }
            CP_COMMIT();
            CP_WAIT(1);
        } else {
            CP_WAIT(0);
        }
        __syncthreads();

        float acc[2][4][4];
        #pragma unroll
        for (int mf = 0; mf < 2; mf++)
            #pragma unroll
            for (int nf = 0; nf < 4; nf++)
                #pragma unroll
                for (int q = 0; q < 4; q++) acc[mf][nf][q] = 0.f;

        unsigned bB = smb + B_OFF + (t & 1) * 65536;

        // ---- mainloop with fragment double-buffering (LDSM overlaps MMA) ----
        unsigned afr[2][2][4], bfr[2][8];
        #pragma unroll
        for (int mf = 0; mf < 2; mf++)
            ldsm4(afr[0][mf][0], afr[0][mf][1], afr[0][mf][2], afr[0][mf][3],
                  aBase[mf] + (0 ^ xA[mf]));
        #pragma unroll
        for (int nfp = 0; nfp < 2; nfp++) {
            unsigned q0, q1, q2, q3;
            ldsm4(q0, q1, q2, q3, bB + bRow[nfp] + (0 ^ xB[nfp]));
            bfr[0][nfp * 4 + 0] = q0; bfr[0][nfp * 4 + 1] = q2;
            bfr[0][nfp * 4 + 2] = q1; bfr[0][nfp * 4 + 3] = q3;
        }
        #pragma unroll
        for (int ks = 0; ks < 16; ks++) {
            const int cur = ks & 1, nxt = cur ^ 1;
            if (ks < 15) {
                #pragma unroll
                for (int mf = 0; mf < 2; mf++)
                    ldsm4(afr[nxt][mf][0], afr[nxt][mf][1], afr[nxt][mf][2], afr[nxt][mf][3],
                          aBase[mf] + (((ks + 1) << 5) ^ xA[mf]));
                #pragma unroll
                for (int nfp = 0; nfp < 2; nfp++) {
                    unsigned q0, q1, q2, q3;
                    ldsm4(q0, q1, q2, q3, bB + bRow[nfp] + (((ks + 1) << 5) ^ xB[nfp]));
                    bfr[nxt][nfp * 4 + 0] = q0; bfr[nxt][nfp * 4 + 1] = q2;
                    bfr[nxt][nfp * 4 + 2] = q1; bfr[nxt][nfp * 4 + 3] = q3;
                }
            }
            #pragma unroll
            for (int mf = 0; mf < 2; mf++)
                #pragma unroll
                for (int nf = 0; nf < 4; nf++)
                    mma16816(acc[mf][nf], afr[cur][mf], bfr[cur][nf * 2], bfr[cur][nf * 2 + 1]);
        }

        // ---- epilogue: store fp16 scores + track per-row fp32 min ----
        #pragma unroll
        for (int mf = 0; mf < 2; mf++) {
            int r0l = wm * 32 + mf * 16 + (l >> 2);
            int r1l = r0l + 8;
            int gr0 = row0 + r0l;
            float mn0 = CUDART_INF_F, mn1 = CUDART_INF_F;
            #pragma unroll
            for (int nf = 0; nf < 4; nf++) {
                int gc = t * 128 + wn * 32 + nf * 8 + (l & 3) * 2;
                float se0 = se_sm[gc], se1 = se_sm[gc + 1];
                float s00 = fmaf(-2.f, acc[mf][nf][0], se0);
                float s01 = fmaf(-2.f, acc[mf][nf][1], se1);
                float s10 = fmaf(-2.f, acc[mf][nf][2], se0);
                float s11 = fmaf(-2.f, acc[mf][nf][3], se1);
                mn0 = fminf(mn0, fminf(s00, s01));
                mn1 = fminf(mn1, fminf(s10, s11));
                *(__half2*)(g_t + (size_t)gr0 * NE + gc)       = __floats2half2_rn(s00, s01);
                *(__half2*)(g_t + (size_t)(gr0 + 8) * NE + gc) = __floats2half2_rn(s10, s11);
            }
            mn0 = fminf(mn0, __shfl_xor_sync(0xffffffffu, mn0, 1));
            mn0 = fminf(mn0, __shfl_xor_sync(0xffffffffu, mn0, 2));
            mn1 = fminf(mn1, __shfl_xor_sync(0xffffffffu, mn1, 1));
            mn1 = fminf(mn1, __shfl_xor_sync(0xffffffffu, mn1, 2));
            if ((l & 3) == 0) {
                atomicMin(&sm_min[r0l], fmapu(mn0));
                atomicMin(&sm_min[r1l], fmapu(mn1));
            }
        }
        __syncthreads();
    }

    if (tid < 128) g_amin[row0 + tid] = funmapu(sm_min[tid]);
}

// ================= rescore: scan scores vs FINAL min, exact fp32 on shortlist =================
__global__ void __launch_bounds__(256) rescore_kernel(const float* __restrict__ emb,
                                                      float* __restrict__ out) {
    __shared__ int    s_cand[8][RCAP];
    __shared__ int    s_cnt[8];
    __shared__ double s_wd[8];
    int w = threadIdx.x >> 5, l = threadIdx.x & 31;
    int row = blockIdx.x * 8 + w;
    if (l == 0) s_cnt[w] = 0;
    __syncwarp();

    // scan fp16 scores against final-min threshold (tight: ~3 candidates expected)
    float thr = g_amin[row] + MARGIN;
    const uint2* tp = (const uint2*)(g_t + (size_t)row * NE);
    #pragma unroll
    for (int q = 0; q < 8; q++) {
        uint2 u = tp[q * 32 + l];
        int cbase = (q * 32 + l) * 4;
        __half2 h0 = *(__half2*)&u.x, h1 = *(__half2*)&u.y;
        float f0 = __low2float(h0), f1 = __high2float(h0);
        float f2 = __low2float(h1), f3 = __high2float(h1);
        if (f0 <= thr) { int p = atomicAdd(&s_cnt[w], 1); if (p < RCAP) s_cand[w][p] = cbase; }
        if (f1 <= thr) { int p = atomicAdd(&s_cnt[w], 1); if (p < RCAP) s_cand[w][p] = cbase + 1; }
        if (f2 <= thr) { int p = atomicAdd(&s_cnt[w], 1); if (p < RCAP) s_cand[w][p] = cbase + 2; }
        if (f3 <= thr) { int p = atomicAdd(&s_cnt[w], 1); if (p < RCAP) s_cand[w][p] = cbase + 3; }
    }
    __syncwarp();
    int cnt = s_cnt[w];
    bool ovf = (cnt > RCAP);
    int n = ovf ? NE : cnt;

    const float* zp = g_zrm + (size_t)row * CDIM;

    // per-row sz, R1-exact: 8 strided partials (mul+add), ordered combine
    int y = l & 7;
    float p = 0.f;
    #pragma unroll 8
    for (int i = 0; i < 32; i++) {
        float v = zp[y + 8 * i];
        p = __fadd_rn(p, __fmul_rn(v, v));
    }
    int base = l & 24;
    float szr = __shfl_sync(0xffffffffu, p, base);
    #pragma unroll
    for (int yy = 1; yy < 8; yy++)
        szr = __fadd_rn(szr, __shfl_sync(0xffffffffu, p, base + yy));
    szr = __shfl_sync(0xffffffffu, szr, 0);

    float bd = CUDART_INF_F; int bj = 0x7fffffff;
    for (int i = l; i < n; i += 32) {
        int j = ovf ? i : s_cand[w][i];
        const float* ep = emb + (size_t)j * CDIM;
        float acc = 0.f;
        #pragma unroll 8
        for (int k = 0; k < 256; k++) acc = fmaf(zp[k], ep[k], acc);   // exact R1 order
        float d = fmaf(-2.f, acc, __fadd_rn(szr, g_se[j]));            // exact R1 rounding
        if (d < bd || (d == bd && j < bj)) { bd = d; bj = j; }
    }
    #pragma unroll
    for (int off = 16; off; off >>= 1) {
        float od = __shfl_down_sync(0xffffffffu, bd, off);
        int   oj = __shfl_down_sync(0xffffffffu, bj, off);
        if (od < bd || (od == bd && oj < bj)) { bd = od; bj = oj; }
    }
    if (l == 0) { out[row] = (float)bj; s_wd[w] = (double)bd; }
    __syncthreads();
    if (threadIdx.x == 0) {
        double q = 0.0;
        #pragma unroll
        for (int i = 0; i < 8; i++) q += s_wd[i];
        g_partial[blockIdx.x] = q;
    }
}

// ================= loss finalize =================
__global__ void loss2_kernel(float* __restrict__ out, int out_size) {
    __shared__ double s[1024];
    int t = threadIdx.x;
    s[t] = g_partial[t] + g_partial[t + 1024] + g_partial[t + 2048] + g_partial[t + 3072];
    __syncthreads();
    for (int off = 512; off; off >>= 1) {
        if (t < off) s[t] += s[t + off];
        __syncthreads();
    }
    if (t == 0 && out_size > NROW) {
        float m = (float)(s[0] / (double)((size_t)NROW * CDIM));
        out[NROW] = m + 0.25f * m;
    }
}

extern "C" void kernel_launch(void* const* d_in, const int* in_sizes, int n_in,
                              void* d_out, int out_size) {
    const float* z   = (const float*)d_in[0];   // (32,256,32,32) fp32
    const float* emb = (const float*)d_in[1];   // (1024,256)     fp32
    float* out = (float*)d_out;

    eprep_kernel<<<1024, 256>>>(emb);
    se_kernel<<<1024, 64>>>(emb);
    pinit_kernel<<<16, 256>>>();                 // spacer: gemm lands in profiled slot #4

    static int smem_set = 0;
    if (!smem_set) {
        cudaFuncSetAttribute(gemm_kernel, cudaFuncAttributeMaxDynamicSharedMemorySize, SMEM_T);
        smem_set = 1;
    }
    gemm_kernel<<<256, 512, SMEM_T>>>(z);

    rescore_kernel<<<4096, 256>>>(emb, out);
    loss2_kernel<<<1, 1024>>>(out, out_size);
}

// round 9
// speedup vs baseline: 1.2458x; 1.2458x over previous
#include <cuda_runtime.h>
#include <cuda_bf16.h>
#include <cuda_fp16.h>
#include <math_constants.h>

#define NROW 32768
#define CDIM 256
#define NE   1024
#define MARGIN 4e-3f
#define CAP  48

// ---- static device scratch (allocation-free rule) ----
__device__ float          g_zrm[(size_t)NROW * CDIM];   // z row-major [n][c] fp32 (written by gemm)
__device__ __nv_bfloat16  g_ebf[(size_t)NE * CDIM];     // bf16(emb) [j][k]
__device__ float          g_se[NE];
__device__ int            g_cnt[NROW];
__device__ unsigned short g_cand[(size_t)NROW * CAP];
__device__ double         g_partial[4096];

// ================= PTX helpers (baseline sm_80 ISA only) =================
__device__ __forceinline__ unsigned smem_u32(const void* p) {
    unsigned a;
    asm("{ .reg .u64 t; cvta.to.shared.u64 t, %1; cvt.u32.u64 %0, t; }" : "=r"(a) : "l"(p));
    return a;
}
__device__ __forceinline__ void cp16(unsigned dst, const void* src) {
    asm volatile("cp.async.cg.shared.global [%0], [%1], 16;" :: "r"(dst), "l"(src));
}
#define CP_COMMIT() asm volatile("cp.async.commit_group;" ::: "memory")
#define CP_WAIT(n)  asm volatile("cp.async.wait_group %0;" :: "n"(n) : "memory")

__device__ __forceinline__ void ldsm4(unsigned& r0, unsigned& r1, unsigned& r2, unsigned& r3,
                                      unsigned addr) {
    asm volatile("ldmatrix.sync.aligned.m8n8.x4.shared.b16 {%0,%1,%2,%3}, [%4];"
        : "=r"(r0), "=r"(r1), "=r"(r2), "=r"(r3) : "r"(addr));
}
__device__ __forceinline__ void mma16816(float* c, const unsigned* a, unsigned b0, unsigned b1) {
    asm volatile("mma.sync.aligned.m16n8k16.row.col.f32.bf16.bf16.f32 "
        "{%0,%1,%2,%3}, {%4,%5,%6,%7}, {%8,%9}, {%0,%1,%2,%3};"
        : "+f"(c[0]), "+f"(c[1]), "+f"(c[2]), "+f"(c[3])
        : "r"(a[0]), "r"(a[1]), "r"(a[2]), "r"(a[3]), "r"(b0), "r"(b1));
}
__device__ __forceinline__ unsigned fmapu(float f) {
    unsigned b = __float_as_uint(f);
    return (b & 0x80000000u) ? ~b : (b | 0x80000000u);
}
__device__ __forceinline__ float funmapu(unsigned u) {
    return (u & 0x80000000u) ? __uint_as_float(u & 0x7fffffffu) : __uint_as_float(~u);
}

// ================= prep kernels =================
__global__ void eprep_kernel(const float* __restrict__ e) {
    int i = blockIdx.x * 256 + threadIdx.x;
    g_ebf[i] = __float2bfloat16(e[i]);
}

// per-code norms (verbatim R1 rounding — known-passing)
__global__ void se_kernel(const float* __restrict__ e) {
    int j = blockIdx.x;
    float4 v = *(const float4*)&e[j * 256 + threadIdx.x * 4];
    float s = __fadd_rn(__fadd_rn(__fmul_rn(v.x,v.x), __fmul_rn(v.y,v.y)),
                        __fadd_rn(__fmul_rn(v.z,v.z), __fmul_rn(v.w,v.w)));
    for (int off = 16; off; off >>= 1) s += __shfl_down_sync(0xffffffffu, s, off);
    __shared__ float r2[2];
    if ((threadIdx.x & 31) == 0) r2[threadIdx.x >> 5] = s;
    __syncthreads();
    if (threadIdx.x == 0) g_se[j] = __fadd_rn(r2[0], r2[1]);
}

// ================= HMMA scoring + online shortlist (single pass, tight margin) =================
// smem: se 4KB | A 64KB | B 2x64KB (stage reuse) | min 512B | cnt 512B | lists 12KB
#define SE_OFF   0
#define A_OFF    4096
#define B_OFF    (4096 + 65536)
#define MIN_OFF  (B_OFF + 131072)          // 200704
#define CNT_OFF  (MIN_OFF + 512)
#define LIST_OFF (CNT_OFF + 512)
#define SMEM_T   (LIST_OFF + 128 * CAP * 2)  // 214016

__global__ void __launch_bounds__(512) gemm_kernel(const float* __restrict__ z) {
    extern __shared__ char sm[];
    unsigned smb = smem_u32(sm);
    const int tid = threadIdx.x, l = tid & 31, w = tid >> 5;
    const int wm = w & 3, wn = w >> 2;           // 4x4 warp grid, 32x32 tiles
    const int row0 = blockIdx.x * 128;
    float* se_sm = (float*)(sm + SE_OFF);
    unsigned* sm_min = (unsigned*)(sm + MIN_OFF);
    int* sm_cnt = (int*)(sm + CNT_OFF);
    unsigned short* sm_list = (unsigned short*)(sm + LIST_OFF);

    if (tid < 256) ((float4*)se_sm)[tid] = ((const float4*)g_se)[tid];
    if (tid < 128) { sm_min[tid] = 0xFFFFFFFFu; sm_cnt[tid] = 0; }

    // ---- phase 1: load z slice from ORIGINAL layout, transpose via staging;
    //      emit fp32 zrm tile (for rescore) + bf16 A tile (swizzled) ----
    {
        const int b = row0 >> 10, hw0 = row0 & 1023;
        float* stg = (float*)(sm + B_OFF) + w * (36 * 32);   // 4608B per warp
        #pragma unroll
        for (int tt = 0; tt < 2; tt++) {
            int ti = w * 2 + tt;            // 32 tiles: ci 0..7 (c), hi 0..3 (hw)
            int ci = ti >> 2, hi = ti & 3;
            #pragma unroll
            for (int i = 0; i < 8; i++) {
                int cl = i * 4 + (l >> 3);
                float4 v = *(const float4*)&z[((size_t)b << 18) + (size_t)(ci * 32 + cl) * 1024
                                              + hw0 + hi * 32 + (l & 7) * 4];
                *(float4*)&stg[cl * 36 + (l & 7) * 4] = v;
            }
            __syncwarp();
            int c = ci * 32 + l;
            #pragma unroll
            for (int rr = 0; rr < 32; rr++) {
                float v = stg[l * 36 + rr];
                int r = hi * 32 + rr;
                g_zrm[(size_t)(row0 + r) * 256 + c] = v;
                *(__nv_bfloat16*)(sm + A_OFF + r * 512 + ((c * 2) ^ ((r & 7) << 4))) =
                    __float2bfloat16(v);
            }
            __syncwarp();
        }
    }
    __syncthreads();   // A ready; staging region free for B

    // ---- B chunk 0 via cp.async ----
    const char* esrc = (const char*)g_ebf;
    #pragma unroll
    for (int i = 0; i < 8; i++) {
        int f = tid + i * 512, r = f >> 5, kb16 = f & 31;
        cp16(smb + B_OFF + r * 512 + ((kb16 * 16) ^ ((r & 7) << 4)),
             esrc + (size_t)r * 512 + kb16 * 16);
    }
    CP_COMMIT();

    const unsigned c16 = ((l >> 4) & 1) * 16;
    unsigned aBase[2], xA[2];
    #pragma unroll
    for (int mf = 0; mf < 2; mf++) {
        int r = wm * 32 + mf * 16 + (l & 15);
        aBase[mf] = smb + A_OFF + r * 512;
        xA[mf] = c16 ^ ((r & 7) << 4);
    }
    unsigned bRow[2], xB[2];
    #pragma unroll
    for (int nfp = 0; nfp < 2; nfp++) {
        int r = wn * 32 + nfp * 16 + ((l >> 3) & 1) * 8 + (l & 7);
        bRow[nfp] = r * 512;
        xB[nfp] = c16 ^ ((r & 7) << 4);
    }

    for (int t = 0; t < 8; t++) {
        if (t < 7) {
            const char* src = esrc + (size_t)(t + 1) * 128 * 512;
            unsigned dstb = smb + B_OFF + ((t + 1) & 1) * 65536;
            #pragma unroll
            for (int i = 0; i < 8; i++) {
                int f = tid + i * 512, r = f >> 5, kb16 = f & 31;
                cp16(dstb + r * 512 + ((kb16 * 16) ^ ((r & 7) << 4)),
                     src + (size_t)r * 512 + kb16 * 16);
            }
            CP_COMMIT();
            CP_WAIT(1);
        } else {
            CP_WAIT(0);
        }
        __syncthreads();

        float acc[2][4][4];
        #pragma unroll
        for (int mf = 0; mf < 2; mf++)
            #pragma unroll
            for (int nf = 0; nf < 4; nf++)
                #pragma unroll
                for (int q = 0; q < 4; q++) acc[mf][nf][q] = 0.f;

        unsigned bB = smb + B_OFF + (t & 1) * 65536;

        // ---- mainloop with fragment double-buffering (LDSM overlaps MMA) ----
        unsigned afr[2][2][4], bfr[2][8];
        #pragma unroll
        for (int mf = 0; mf < 2; mf++)
            ldsm4(afr[0][mf][0], afr[0][mf][1], afr[0][mf][2], afr[0][mf][3],
                  aBase[mf] + (0 ^ xA[mf]));
        #pragma unroll
        for (int nfp = 0; nfp < 2; nfp++) {
            unsigned q0, q1, q2, q3;
            ldsm4(q0, q1, q2, q3, bB + bRow[nfp] + (0 ^ xB[nfp]));
            bfr[0][nfp * 4 + 0] = q0; bfr[0][nfp * 4 + 1] = q2;
            bfr[0][nfp * 4 + 2] = q1; bfr[0][nfp * 4 + 3] = q3;
        }
        #pragma unroll
        for (int ks = 0; ks < 16; ks++) {
            const int cur = ks & 1, nxt = cur ^ 1;
            if (ks < 15) {
                #pragma unroll
                for (int mf = 0; mf < 2; mf++)
                    ldsm4(afr[nxt][mf][0], afr[nxt][mf][1], afr[nxt][mf][2], afr[nxt][mf][3],
                          aBase[mf] + (((ks + 1) << 5) ^ xA[mf]));
                #pragma unroll
                for (int nfp = 0; nfp < 2; nfp++) {
                    unsigned q0, q1, q2, q3;
                    ldsm4(q0, q1, q2, q3, bB + bRow[nfp] + (((ks + 1) << 5) ^ xB[nfp]));
                    bfr[nxt][nfp * 4 + 0] = q0; bfr[nxt][nfp * 4 + 1] = q2;
                    bfr[nxt][nfp * 4 + 2] = q1; bfr[nxt][nfp * 4 + 3] = q3;
                }
            }
            #pragma unroll
            for (int mf = 0; mf < 2; mf++)
                #pragma unroll
                for (int nf = 0; nf < 4; nf++)
                    mma16816(acc[mf][nf], afr[cur][mf], bfr[cur][nf * 2], bfr[cur][nf * 2 + 1]);
        }

        // ---- online shortlist epilogue (running min; tight 4e-3 margin) ----
        #pragma unroll
        for (int mf = 0; mf < 2; mf++) {
            int r0l = wm * 32 + mf * 16 + (l >> 2);
            int r1l = r0l + 8;
            float mn0 = CUDART_INF_F, mn1 = CUDART_INF_F;
            #pragma unroll
            for (int nf = 0; nf < 4; nf++) {
                int gc = t * 128 + wn * 32 + nf * 8 + (l & 3) * 2;
                float se0 = se_sm[gc], se1 = se_sm[gc + 1];
                mn0 = fminf(mn0, fminf(fmaf(-2.f, acc[mf][nf][0], se0),
                                       fmaf(-2.f, acc[mf][nf][1], se1)));
                mn1 = fminf(mn1, fminf(fmaf(-2.f, acc[mf][nf][2], se0),
                                       fmaf(-2.f, acc[mf][nf][3], se1)));
            }
            mn0 = fminf(mn0, __shfl_xor_sync(0xffffffffu, mn0, 1));
            mn0 = fminf(mn0, __shfl_xor_sync(0xffffffffu, mn0, 2));
            mn1 = fminf(mn1, __shfl_xor_sync(0xffffffffu, mn1, 1));
            mn1 = fminf(mn1, __shfl_xor_sync(0xffffffffu, mn1, 2));
            if ((l & 3) == 0) {
                atomicMin(&sm_min[r0l], fmapu(mn0));
                atomicMin(&sm_min[r1l], fmapu(mn1));
            }
            __syncwarp();
            float thr0 = fminf(funmapu(((volatile unsigned*)sm_min)[r0l]), mn0) + MARGIN;
            float thr1 = fminf(funmapu(((volatile unsigned*)sm_min)[r1l]), mn1) + MARGIN;
            #pragma unroll
            for (int nf = 0; nf < 4; nf++) {
                int gc = t * 128 + wn * 32 + nf * 8 + (l & 3) * 2;
                float se0 = se_sm[gc], se1 = se_sm[gc + 1];
                float s00 = fmaf(-2.f, acc[mf][nf][0], se0);
                float s01 = fmaf(-2.f, acc[mf][nf][1], se1);
                float s10 = fmaf(-2.f, acc[mf][nf][2], se0);
                float s11 = fmaf(-2.f, acc[mf][nf][3], se1);
                if (s00 <= thr0) { int p = atomicAdd(&sm_cnt[r0l], 1); if (p < CAP) sm_list[r0l * CAP + p] = (unsigned short)gc; }
                if (s01 <= thr0) { int p = atomicAdd(&sm_cnt[r0l], 1); if (p < CAP) sm_list[r0l * CAP + p] = (unsigned short)(gc + 1); }
                if (s10 <= thr1) { int p = atomicAdd(&sm_cnt[r1l], 1); if (p < CAP) sm_list[r1l * CAP + p] = (unsigned short)gc; }
                if (s11 <= thr1) { int p = atomicAdd(&sm_cnt[r1l], 1); if (p < CAP) sm_list[r1l * CAP + p] = (unsigned short)(gc + 1); }
            }
        }
        __syncthreads();
    }

    // ---- dump shortlists ----
    if (tid < 128) g_cnt[row0 + tid] = sm_cnt[tid];
    unsigned* gl = (unsigned*)&g_cand[(size_t)row0 * CAP];
    unsigned* sl = (unsigned*)sm_list;
    #pragma unroll
    for (int k = 0; k < 6; k++) gl[tid + k * 512] = sl[tid + k * 512];
}

// ================= exact rescore (high occupancy, warp per row) =================
__global__ void __launch_bounds__(256) rescore_kernel(const float* __restrict__ emb,
                                                      float* __restrict__ out) {
    __shared__ double s_wd[8];
    int w = threadIdx.x >> 5, l = threadIdx.x & 31;
    int row = blockIdx.x * 8 + w;
    const float* zp = g_zrm + (size_t)row * CDIM;

    // per-row sz, R1-exact: 8 strided partials (mul+add), ordered combine
    int y = l & 7;
    float p = 0.f;
    #pragma unroll 8
    for (int i = 0; i < 32; i++) {
        float v = zp[y + 8 * i];
        p = __fadd_rn(p, __fmul_rn(v, v));
    }
    int base = l & 24;
    float szr = __shfl_sync(0xffffffffu, p, base);
    #pragma unroll
    for (int yy = 1; yy < 8; yy++)
        szr = __fadd_rn(szr, __shfl_sync(0xffffffffu, p, base + yy));
    szr = __shfl_sync(0xffffffffu, szr, 0);

    int cnt = g_cnt[row];
    bool ovf = (cnt > CAP);
    int n = ovf ? NE : cnt;
    float bd = CUDART_INF_F; int bj = 0x7fffffff;
    for (int i = l; i < n; i += 32) {
        int j = ovf ? i : (int)g_cand[(size_t)row * CAP + i];
        const float* ep = emb + (size_t)j * CDIM;
        float acc = 0.f;
        #pragma unroll 8
        for (int k = 0; k < 256; k++) acc = fmaf(zp[k], ep[k], acc);   // exact R1 order
        float d = fmaf(-2.f, acc, __fadd_rn(szr, g_se[j]));            // exact R1 rounding
        if (d < bd || (d == bd && j < bj)) { bd = d; bj = j; }
    }
    #pragma unroll
    for (int off = 16; off; off >>= 1) {
        float od = __shfl_down_sync(0xffffffffu, bd, off);
        int   oj = __shfl_down_sync(0xffffffffu, bj, off);
        if (od < bd || (od == bd && oj < bj)) { bd = od; bj = oj; }
    }
    if (l == 0) { out[row] = (float)bj; s_wd[w] = (double)bd; }
    __syncthreads();
    if (threadIdx.x == 0) {
        double q = 0.0;
        #pragma unroll
        for (int i = 0; i < 8; i++) q += s_wd[i];
        g_partial[blockIdx.x] = q;
    }
}

// ================= loss finalize =================
__global__ void loss2_kernel(float* __restrict__ out, int out_size) {
    __shared__ double s[1024];
    int t = threadIdx.x;
    s[t] = g_partial[t] + g_partial[t + 1024] + g_partial[t + 2048] + g_partial[t + 3072];
    __syncthreads();
    for (int off = 512; off; off >>= 1) {
        if (t < off) s[t] += s[t + off];
        __syncthreads();
    }
    if (t == 0 && out_size > NROW) {
        float m = (float)(s[0] / (double)((size_t)NROW * CDIM));
        out[NROW] = m + 0.25f * m;
    }
}

extern "C" void kernel_launch(void* const* d_in, const int* in_sizes, int n_in,
                              void* d_out, int out_size) {
    const float* z   = (const float*)d_in[0];   // (32,256,32,32) fp32
    const float* emb = (const float*)d_in[1];   // (1024,256)     fp32
    float* out = (float*)d_out;

    eprep_kernel<<<1024, 256>>>(emb);
    se_kernel<<<1024, 64>>>(emb);

    static int smem_set = 0;
    if (!smem_set) {
        cudaFuncSetAttribute(gemm_kernel, cudaFuncAttributeMaxDynamicSharedMemorySize, SMEM_T);
        smem_set = 1;
    }
    gemm_kernel<<<256, 512, SMEM_T>>>(z);        // slot 3

    rescore_kernel<<<4096, 256>>>(emb, out);     // slot 4 -> profiled this round
    loss2_kernel<<<1, 1024>>>(out, out_size);
}

// round 10
// speedup vs baseline: 2.3980x; 1.9249x over previous
#include <cuda_runtime.h>
#include <cuda_bf16.h>
#include <cuda_fp16.h>
#include <math_constants.h>

#define NROW 32768
#define CDIM 256
#define NE   1024
#define MARGIN 4e-3f
#define CAP  48

// ---- static device scratch (allocation-free rule) ----
__device__ float          g_zrm[(size_t)NROW * CDIM];   // z row-major [n][c] fp32 (written by gemm)
__device__ __nv_bfloat16  g_ebf[(size_t)NE * CDIM];     // bf16(emb) [j][k]
__device__ float          g_se[NE];
__device__ int            g_cnt[NROW];
__device__ unsigned short g_cand[(size_t)NROW * CAP];
__device__ double         g_partial[4096];

// ================= PTX helpers (baseline sm_80 ISA only) =================
__device__ __forceinline__ unsigned smem_u32(const void* p) {
    unsigned a;
    asm("{ .reg .u64 t; cvta.to.shared.u64 t, %1; cvt.u32.u64 %0, t; }" : "=r"(a) : "l"(p));
    return a;
}
__device__ __forceinline__ void cp16(unsigned dst, const void* src) {
    asm volatile("cp.async.cg.shared.global [%0], [%1], 16;" :: "r"(dst), "l"(src));
}
#define CP_COMMIT() asm volatile("cp.async.commit_group;" ::: "memory")
#define CP_WAIT(n)  asm volatile("cp.async.wait_group %0;" :: "n"(n) : "memory")

__device__ __forceinline__ void ldsm4(unsigned& r0, unsigned& r1, unsigned& r2, unsigned& r3,
                                      unsigned addr) {
    asm volatile("ldmatrix.sync.aligned.m8n8.x4.shared.b16 {%0,%1,%2,%3}, [%4];"
        : "=r"(r0), "=r"(r1), "=r"(r2), "=r"(r3) : "r"(addr));
}
__device__ __forceinline__ void mma16816(float* c, const unsigned* a, unsigned b0, unsigned b1) {
    asm volatile("mma.sync.aligned.m16n8k16.row.col.f32.bf16.bf16.f32 "
        "{%0,%1,%2,%3}, {%4,%5,%6,%7}, {%8,%9}, {%0,%1,%2,%3};"
        : "+f"(c[0]), "+f"(c[1]), "+f"(c[2]), "+f"(c[3])
        : "r"(a[0]), "r"(a[1]), "r"(a[2]), "r"(a[3]), "r"(b0), "r"(b1));
}
__device__ __forceinline__ unsigned fmapu(float f) {
    unsigned b = __float_as_uint(f);
    return (b & 0x80000000u) ? ~b : (b | 0x80000000u);
}
__device__ __forceinline__ float funmapu(unsigned u) {
    return (u & 0x80000000u) ? __uint_as_float(u & 0x7fffffffu) : __uint_as_float(~u);
}

// ================= prep kernels =================
__global__ void eprep_kernel(const float* __restrict__ e) {
    int i = blockIdx.x * 256 + threadIdx.x;
    g_ebf[i] = __float2bfloat16(e[i]);
}

// per-code norms (verbatim R1 rounding — known-passing)
__global__ void se_kernel(const float* __restrict__ e) {
    int j = blockIdx.x;
    float4 v = *(const float4*)&e[j * 256 + threadIdx.x * 4];
    float s = __fadd_rn(__fadd_rn(__fmul_rn(v.x,v.x), __fmul_rn(v.y,v.y)),
                        __fadd_rn(__fmul_rn(v.z,v.z), __fmul_rn(v.w,v.w)));
    for (int off = 16; off; off >>= 1) s += __shfl_down_sync(0xffffffffu, s, off);
    __shared__ float r2[2];
    if ((threadIdx.x & 31) == 0) r2[threadIdx.x >> 5] = s;
    __syncthreads();
    if (threadIdx.x == 0) g_se[j] = __fadd_rn(r2[0], r2[1]);
}

// ================= HMMA scoring + shortlist (push w/ running min, FILTER w/ final min) =================
// smem: se 4KB | A 64KB | B 2x64KB (stage reuse) | min 512B | cnt 512B | half-scores 12KB | idx 12KB
#define SE_OFF   0
#define A_OFF    4096
#define B_OFF    (4096 + 65536)
#define MIN_OFF  (B_OFF + 131072)          // 200704
#define CNT_OFF  (MIN_OFF + 512)
#define LH_OFF   (CNT_OFF + 512)           // __half scores [128][CAP]
#define LI_OFF   (LH_OFF + 128 * CAP * 2)  // u16 indices  [128][CAP]
#define SMEM_T   (LI_OFF + 128 * CAP * 2)  // 226304

__global__ void __launch_bounds__(512) gemm_kernel(const float* __restrict__ z) {
    extern __shared__ char sm[];
    unsigned smb = smem_u32(sm);
    const int tid = threadIdx.x, l = tid & 31, w = tid >> 5;
    const int wm = w & 3, wn = w >> 2;           // 4x4 warp grid, 32x32 tiles
    const int row0 = blockIdx.x * 128;
    float* se_sm = (float*)(sm + SE_OFF);
    unsigned* sm_min = (unsigned*)(sm + MIN_OFF);
    int* sm_cnt = (int*)(sm + CNT_OFF);
    __half* sm_lh = (__half*)(sm + LH_OFF);
    unsigned short* sm_li = (unsigned short*)(sm + LI_OFF);

    if (tid < 256) ((float4*)se_sm)[tid] = ((const float4*)g_se)[tid];
    if (tid < 128) { sm_min[tid] = 0xFFFFFFFFu; sm_cnt[tid] = 0; }

    // ---- phase 1: load z slice from ORIGINAL layout, transpose via staging;
    //      emit fp32 zrm tile (for rescore) + bf16 A tile (swizzled) ----
    {
        const int b = row0 >> 10, hw0 = row0 & 1023;
        float* stg = (float*)(sm + B_OFF) + w * (36 * 32);   // 4608B per warp
        #pragma unroll
        for (int tt = 0; tt < 2; tt++) {
            int ti = w * 2 + tt;            // 32 tiles: ci 0..7 (c), hi 0..3 (hw)
            int ci = ti >> 2, hi = ti & 3;
            #pragma unroll
            for (int i = 0; i < 8; i++) {
                int cl = i * 4 + (l >> 3);
                float4 v = *(const float4*)&z[((size_t)b << 18) + (size_t)(ci * 32 + cl) * 1024
                                              + hw0 + hi * 32 + (l & 7) * 4];
                *(float4*)&stg[cl * 36 + (l & 7) * 4] = v;
            }
            __syncwarp();
            int c = ci * 32 + l;
            #pragma unroll
            for (int rr = 0; rr < 32; rr++) {
                float v = stg[l * 36 + rr];
                int r = hi * 32 + rr;
                g_zrm[(size_t)(row0 + r) * 256 + c] = v;
                *(__nv_bfloat16*)(sm + A_OFF + r * 512 + ((c * 2) ^ ((r & 7) << 4))) =
                    __float2bfloat16(v);
            }
            __syncwarp();
        }
    }
    __syncthreads();   // A ready; staging region free for B

    // ---- B chunk 0 via cp.async ----
    const char* esrc = (const char*)g_ebf;
    #pragma unroll
    for (int i = 0; i < 8; i++) {
        int f = tid + i * 512, r = f >> 5, kb16 = f & 31;
        cp16(smb + B_OFF + r * 512 + ((kb16 * 16) ^ ((r & 7) << 4)),
             esrc + (size_t)r * 512 + kb16 * 16);
    }
    CP_COMMIT();

    const unsigned c16 = ((l >> 4) & 1) * 16;
    unsigned aBase[2], xA[2];
    #pragma unroll
    for (int mf = 0; mf < 2; mf++) {
        int r = wm * 32 + mf * 16 + (l & 15);
        aBase[mf] = smb + A_OFF + r * 512;
        xA[mf] = c16 ^ ((r & 7) << 4);
    }
    unsigned bRow[2], xB[2];
    #pragma unroll
    for (int nfp = 0; nfp < 2; nfp++) {
        int r = wn * 32 + nfp * 16 + ((l >> 3) & 1) * 8 + (l & 7);
        bRow[nfp] = r * 512;
        xB[nfp] = c16 ^ ((r & 7) << 4);
    }

    for (int t = 0; t < 8; t++) {
        if (t < 7) {
            const char* src = esrc + (size_t)(t + 1) * 128 * 512;
            unsigned dstb = smb + B_OFF + ((t + 1) & 1) * 65536;
            #pragma unroll
            for (int i = 0; i < 8; i++) {
                int f = tid + i * 512, r = f >> 5, kb16 = f & 31;
                cp16(dstb + r * 512 + ((kb16 * 16) ^ ((r & 7) << 4)),
                     src + (size_t)r * 512 + kb16 * 16);
            }
            CP_COMMIT();
            CP_WAIT(1);
        } else {
            CP_WAIT(0);
        }
        __syncthreads();

        float acc[2][4][4];
        #pragma unroll
        for (int mf = 0; mf < 2; mf++)
            #pragma unroll
            for (int nf = 0; nf < 4; nf++)
                #pragma unroll
                for (int q = 0; q < 4; q++) acc[mf][nf][q] = 0.f;

        unsigned bB = smb + B_OFF + (t & 1) * 65536;

        // ---- mainloop with fragment double-buffering (LDSM overlaps MMA) ----
        unsigned afr[2][2][4], bfr[2][8];
        #pragma unroll
        for (int mf = 0; mf < 2; mf++)
            ldsm4(afr[0][mf][0], afr[0][mf][1], afr[0][mf][2], afr[0][mf][3],
                  aBase[mf] + (0 ^ xA[mf]));
        #pragma unroll
        for (int nfp = 0; nfp < 2; nfp++) {
            unsigned q0, q1, q2, q3;
            ldsm4(q0, q1, q2, q3, bB + bRow[nfp] + (0 ^ xB[nfp]));
            bfr[0][nfp * 4 + 0] = q0; bfr[0][nfp * 4 + 1] = q2;
            bfr[0][nfp * 4 + 2] = q1; bfr[0][nfp * 4 + 3] = q3;
        }
        #pragma unroll
        for (int ks = 0; ks < 16; ks++) {
            const int cur = ks & 1, nxt = cur ^ 1;
            if (ks < 15) {
                #pragma unroll
                for (int mf = 0; mf < 2; mf++)
                    ldsm4(afr[nxt][mf][0], afr[nxt][mf][1], afr[nxt][mf][2], afr[nxt][mf][3],
                          aBase[mf] + (((ks + 1) << 5) ^ xA[mf]));
                #pragma unroll
                for (int nfp = 0; nfp < 2; nfp++) {
                    unsigned q0, q1, q2, q3;
                    ldsm4(q0, q1, q2, q3, bB + bRow[nfp] + (((ks + 1) << 5) ^ xB[nfp]));
                    bfr[nxt][nfp * 4 + 0] = q0; bfr[nxt][nfp * 4 + 1] = q2;
                    bfr[nxt][nfp * 4 + 2] = q1; bfr[nxt][nfp * 4 + 3] = q3;
                }
            }
            #pragma unroll
            for (int mf = 0; mf < 2; mf++)
                #pragma unroll
                for (int nf = 0; nf < 4; nf++)
                    mma16816(acc[mf][nf], afr[cur][mf], bfr[cur][nf * 2], bfr[cur][nf * 2 + 1]);
        }

        // ---- epilogue: running-min push (score+idx recorded) ----
        #pragma unroll
        for (int mf = 0; mf < 2; mf++) {
            int r0l = wm * 32 + mf * 16 + (l >> 2);
            int r1l = r0l + 8;
            float mn0 = CUDART_INF_F, mn1 = CUDART_INF_F;
            #pragma unroll
            for (int nf = 0; nf < 4; nf++) {
                int gc = t * 128 + wn * 32 + nf * 8 + (l & 3) * 2;
                float se0 = se_sm[gc], se1 = se_sm[gc + 1];
                mn0 = fminf(mn0, fminf(fmaf(-2.f, acc[mf][nf][0], se0),
                                       fmaf(-2.f, acc[mf][nf][1], se1)));
                mn1 = fminf(mn1, fminf(fmaf(-2.f, acc[mf][nf][2], se0),
                                       fmaf(-2.f, acc[mf][nf][3], se1)));
            }
            mn0 = fminf(mn0, __shfl_xor_sync(0xffffffffu, mn0, 1));
            mn0 = fminf(mn0, __shfl_xor_sync(0xffffffffu, mn0, 2));
            mn1 = fminf(mn1, __shfl_xor_sync(0xffffffffu, mn1, 1));
            mn1 = fminf(mn1, __shfl_xor_sync(0xffffffffu, mn1, 2));
            if ((l & 3) == 0) {
                atomicMin(&sm_min[r0l], fmapu(mn0));
                atomicMin(&sm_min[r1l], fmapu(mn1));
            }
            __syncwarp();
            float thr0 = fminf(funmapu(((volatile unsigned*)sm_min)[r0l]), mn0) + MARGIN;
            float thr1 = fminf(funmapu(((volatile unsigned*)sm_min)[r1l]), mn1) + MARGIN;
            #pragma unroll
            for (int nf = 0; nf < 4; nf++) {
                int gc = t * 128 + wn * 32 + nf * 8 + (l & 3) * 2;
                float se0 = se_sm[gc], se1 = se_sm[gc + 1];
                float s00 = fmaf(-2.f, acc[mf][nf][0], se0);
                float s01 = fmaf(-2.f, acc[mf][nf][1], se1);
                float s10 = fmaf(-2.f, acc[mf][nf][2], se0);
                float s11 = fmaf(-2.f, acc[mf][nf][3], se1);
                if (s00 <= thr0) { int p = atomicAdd(&sm_cnt[r0l], 1); if (p < CAP) { sm_lh[r0l * CAP + p] = __float2half_rn(s00); sm_li[r0l * CAP + p] = (unsigned short)gc; } }
                if (s01 <= thr0) { int p = atomicAdd(&sm_cnt[r0l], 1); if (p < CAP) { sm_lh[r0l * CAP + p] = __float2half_rn(s01); sm_li[r0l * CAP + p] = (unsigned short)(gc + 1); } }
                if (s10 <= thr1) { int p = atomicAdd(&sm_cnt[r1l], 1); if (p < CAP) { sm_lh[r1l * CAP + p] = __float2half_rn(s10); sm_li[r1l * CAP + p] = (unsigned short)gc; } }
                if (s11 <= thr1) { int p = atomicAdd(&sm_cnt[r1l], 1); if (p < CAP) { sm_lh[r1l * CAP + p] = __float2half_rn(s11); sm_li[r1l * CAP + p] = (unsigned short)(gc + 1); } }
            }
        }
        __syncthreads();
    }

    // ---- tail: re-filter lists against FINAL min, ballot-compact, dump ----
    #pragma unroll 1
    for (int rr = 0; rr < 8; rr++) {
        int r = w * 8 + rr;
        int row = row0 + r;
        int cntp = sm_cnt[r];
        if (cntp > CAP) { if (l == 0) g_cnt[row] = 0x7fffffff; continue; }
        float thr = funmapu(sm_min[r]) + (MARGIN + 2.5e-4f);   // slack: fp16 rounding of stored score
        int pos = 0;
        for (int b2 = 0; b2 < cntp; b2 += 32) {
            int i = b2 + l;
            bool keep = false;
            unsigned short idx = 0;
            if (i < cntp) {
                keep = (__half2float(sm_lh[r * CAP + i]) <= thr);
                idx = sm_li[r * CAP + i];
            }
            unsigned m = __ballot_sync(0xffffffffu, keep);
            if (keep) g_cand[(size_t)row * CAP + pos + __popc(m & ((1u << l) - 1))] = idx;
            pos += __popc(m);
        }
        if (l == 0) g_cnt[row] = pos;
    }
}

// ================= exact rescore (tight lists, float4 loads, R1-exact order) =================
__global__ void __launch_bounds__(256) rescore_kernel(const float* __restrict__ emb,
                                                      float* __restrict__ out) {
    __shared__ double s_wd[8];
    int w = threadIdx.x >> 5, l = threadIdx.x & 31;
    int row = blockIdx.x * 8 + w;
    const float* zp = g_zrm + (size_t)row * CDIM;

    // per-row sz, R1-exact: 8 strided partials (mul+add), ordered combine
    int y = l & 7;
    float p = 0.f;
    #pragma unroll 8
    for (int i = 0; i < 32; i++) {
        float v = zp[y + 8 * i];
        p = __fadd_rn(p, __fmul_rn(v, v));
    }
    int base = l & 24;
    float szr = __shfl_sync(0xffffffffu, p, base);
    #pragma unroll
    for (int yy = 1; yy < 8; yy++)
        szr = __fadd_rn(szr, __shfl_sync(0xffffffffu, p, base + yy));
    szr = __shfl_sync(0xffffffffu, szr, 0);

    int cnt = g_cnt[row];
    bool ovf = (cnt > CAP);
    int n = ovf ? NE : cnt;
    const float4* zp4 = (const float4*)zp;
    float bd = CUDART_INF_F; int bj = 0x7fffffff;
    for (int i = l; i < n; i += 32) {
        int j = ovf ? i : (int)g_cand[(size_t)row * CAP + i];
        const float4* ep4 = (const float4*)(emb + (size_t)j * CDIM);
        float acc = 0.f;
        #pragma unroll 8
        for (int k4 = 0; k4 < 64; k4++) {            // same sequential order as R1, vector loads
            float4 zv = zp4[k4];
            float4 ev = ep4[k4];
            acc = fmaf(zv.x, ev.x, acc);
            acc = fmaf(zv.y, ev.y, acc);
            acc = fmaf(zv.z, ev.z, acc);
            acc = fmaf(zv.w, ev.w, acc);
        }
        float d = fmaf(-2.f, acc, __fadd_rn(szr, g_se[j]));   // exact R1 rounding
        if (d < bd || (d == bd && j < bj)) { bd = d; bj = j; }
    }
    #pragma unroll
    for (int off = 16; off; off >>= 1) {
        float od = __shfl_down_sync(0xffffffffu, bd, off);
        int   oj = __shfl_down_sync(0xffffffffu, bj, off);
        if (od < bd || (od == bd && oj < bj)) { bd = od; bj = oj; }
    }
    if (l == 0) { out[row] = (float)bj; s_wd[w] = (double)bd; }
    __syncthreads();
    if (threadIdx.x == 0) {
        double q = 0.0;
        #pragma unroll
        for (int i = 0; i < 8; i++) q += s_wd[i];
        g_partial[blockIdx.x] = q;
    }
}

// ================= loss finalize =================
__global__ void loss2_kernel(float* __restrict__ out, int out_size) {
    __shared__ double s[1024];
    int t = threadIdx.x;
    s[t] = g_partial[t] + g_partial[t + 1024] + g_partial[t + 2048] + g_partial[t + 3072];
    __syncthreads();
    for (int off = 512; off; off >>= 1) {
        if (t < off) s[t] += s[t + off];
        __syncthreads();
    }
    if (t == 0 && out_size > NROW) {
        float m = (float)(s[0] / (double)((size_t)NROW * CDIM));
        out[NROW] = m + 0.25f * m;
    }
}

extern "C" void kernel_launch(void* const* d_in, const int* in_sizes, int n_in,
                              void* d_out, int out_size) {
    const float* z   = (const float*)d_in[0];   // (32,256,32,32) fp32
    const float* emb = (const float*)d_in[1];   // (1024,256)     fp32
    float* out = (float*)d_out;

    eprep_kernel<<<1024, 256>>>(emb);
    se_kernel<<<1024, 64>>>(emb);

    static int smem_set = 0;
    if (!smem_set) {
        cudaFuncSetAttribute(gemm_kernel, cudaFuncAttributeMaxDynamicSharedMemorySize, SMEM_T);
        smem_set = 1;
    }
    gemm_kernel<<<256, 512, SMEM_T>>>(z);        // slot 3

    rescore_kernel<<<4096, 256>>>(emb, out);     // slot 4 -> profiled (verify the fix)
    loss2_kernel<<<1, 1024>>>(out, out_size);
}

// round 11
// speedup vs baseline: 2.6961x; 1.1243x over previous
#include <cuda_runtime.h>
#include <cuda_bf16.h>
#include <cuda_fp16.h>
#include <math_constants.h>

#define NROW 32768
#define CDIM 256
#define NE   1024
#define MARGIN 4e-3f
#define CAP  48

// ---- static device scratch (allocation-free rule) ----
__device__ float          g_zrm[(size_t)NROW * CDIM];   // z row-major [n][c] fp32 (written+read by gemm)
__device__ __nv_bfloat16  g_ebf[(size_t)NE * CDIM];     // bf16(emb) [j][k]
__device__ float          g_se[NE];
__device__ double         g_partial[256];

// ================= PTX helpers (baseline sm_80 ISA only) =================
__device__ __forceinline__ unsigned smem_u32(const void* p) {
    unsigned a;
    asm("{ .reg .u64 t; cvta.to.shared.u64 t, %1; cvt.u32.u64 %0, t; }" : "=r"(a) : "l"(p));
    return a;
}
__device__ __forceinline__ void cp16(unsigned dst, const void* src) {
    asm volatile("cp.async.cg.shared.global [%0], [%1], 16;" :: "r"(dst), "l"(src));
}
#define CP_COMMIT() asm volatile("cp.async.commit_group;" ::: "memory")
#define CP_WAIT(n)  asm volatile("cp.async.wait_group %0;" :: "n"(n) : "memory")

__device__ __forceinline__ void ldsm4(unsigned& r0, unsigned& r1, unsigned& r2, unsigned& r3,
                                      unsigned addr) {
    asm volatile("ldmatrix.sync.aligned.m8n8.x4.shared.b16 {%0,%1,%2,%3}, [%4];"
        : "=r"(r0), "=r"(r1), "=r"(r2), "=r"(r3) : "r"(addr));
}
__device__ __forceinline__ void mma16816(float* c, const unsigned* a, unsigned b0, unsigned b1) {
    asm volatile("mma.sync.aligned.m16n8k16.row.col.f32.bf16.bf16.f32 "
        "{%0,%1,%2,%3}, {%4,%5,%6,%7}, {%8,%9}, {%0,%1,%2,%3};"
        : "+f"(c[0]), "+f"(c[1]), "+f"(c[2]), "+f"(c[3])
        : "r"(a[0]), "r"(a[1]), "r"(a[2]), "r"(a[3]), "r"(b0), "r"(b1));
}
__device__ __forceinline__ unsigned fmapu(float f) {
    unsigned b = __float_as_uint(f);
    return (b & 0x80000000u) ? ~b : (b | 0x80000000u);
}
__device__ __forceinline__ float funmapu(unsigned u) {
    return (u & 0x80000000u) ? __uint_as_float(u & 0x7fffffffu) : __uint_as_float(~u);
}

// ================= prep kernels =================
__global__ void eprep_kernel(const float* __restrict__ e) {
    int i = blockIdx.x * 256 + threadIdx.x;
    g_ebf[i] = __float2bfloat16(e[i]);
}

// per-code norms (verbatim R1 rounding — known-passing)
__global__ void se_kernel(const float* __restrict__ e) {
    int j = blockIdx.x;
    float4 v = *(const float4*)&e[j * 256 + threadIdx.x * 4];
    float s = __fadd_rn(__fadd_rn(__fmul_rn(v.x,v.x), __fmul_rn(v.y,v.y)),
                        __fadd_rn(__fmul_rn(v.z,v.z), __fmul_rn(v.w,v.w)));
    for (int off = 16; off; off >>= 1) s += __shfl_down_sync(0xffffffffu, s, off);
    __shared__ float r2[2];
    if ((threadIdx.x & 31) == 0) r2[threadIdx.x >> 5] = s;
    __syncthreads();
    if (threadIdx.x == 0) g_se[j] = __fadd_rn(r2[0], r2[1]);
}

__global__ void pinit_kernel() {   // spacer (gemm -> profiled slot #4) + deterministic init
    g_partial[threadIdx.x] = 0.0;
}

// ================= fused: HMMA scoring + shortlist + exact rescore tail =================
// smem: se 4KB | A 64KB | B 2x64KB (stage/tail reuse) | min 512B | cnt 512B | lh 12KB | li 12KB
#define SE_OFF   0
#define A_OFF    4096
#define B_OFF    (4096 + 65536)
#define MIN_OFF  (B_OFF + 131072)          // 200704
#define CNT_OFF  (MIN_OFF + 512)
#define LH_OFF   (CNT_OFF + 512)           // __half scores [128][CAP]
#define LI_OFF   (LH_OFF + 128 * CAP * 2)  // u16 indices  [128][CAP]
#define SMEM_T   (LI_OFF + 128 * CAP * 2)  // 226304
// tail overlays inside the (dead) B region:
#define RES_OFF  B_OFF                     // u64 res[128]      (1KB)
#define SZV_OFF  (B_OFF + 1024)            // float szv[128]    (512B)
#define OFS_OFF  (B_OFF + 1536)            // int offs[129]
#define WL_OFF   (B_OFF + 4096)            // u32 worklist (cap ~31k entries)

__global__ void __launch_bounds__(512) gemm_kernel(const float* __restrict__ z,
                                                   const float* __restrict__ emb,
                                                   float* __restrict__ out) {
    extern __shared__ char sm[];
    unsigned smb = smem_u32(sm);
    const int tid = threadIdx.x, l = tid & 31, w = tid >> 5;
    const int wm = w & 3, wn = w >> 2;           // 4x4 warp grid, 32x32 tiles
    const int row0 = blockIdx.x * 128;
    float* se_sm = (float*)(sm + SE_OFF);
    unsigned* sm_min = (unsigned*)(sm + MIN_OFF);
    int* sm_cnt = (int*)(sm + CNT_OFF);
    __half* sm_lh = (__half*)(sm + LH_OFF);
    unsigned short* sm_li = (unsigned short*)(sm + LI_OFF);

    if (tid < 256) ((float4*)se_sm)[tid] = ((const float4*)g_se)[tid];
    if (tid < 128) { sm_min[tid] = 0xFFFFFFFFu; sm_cnt[tid] = 0; }

    // ---- phase 1: load z slice from ORIGINAL layout, transpose via staging;
    //      emit fp32 zrm tile (for rescore) + bf16 A tile (swizzled) ----
    {
        const int b = row0 >> 10, hw0 = row0 & 1023;
        float* stg = (float*)(sm + B_OFF) + w * (36 * 32);   // 4608B per warp
        #pragma unroll
        for (int tt = 0; tt < 2; tt++) {
            int ti = w * 2 + tt;            // 32 tiles: ci 0..7 (c), hi 0..3 (hw)
            int ci = ti >> 2, hi = ti & 3;
            #pragma unroll
            for (int i = 0; i < 8; i++) {
                int cl = i * 4 + (l >> 3);
                float4 v = *(const float4*)&z[((size_t)b << 18) + (size_t)(ci * 32 + cl) * 1024
                                              + hw0 + hi * 32 + (l & 7) * 4];
                *(float4*)&stg[cl * 36 + (l & 7) * 4] = v;
            }
            __syncwarp();
            int c = ci * 32 + l;
            #pragma unroll
            for (int rr = 0; rr < 32; rr++) {
                float v = stg[l * 36 + rr];
                int r = hi * 32 + rr;
                g_zrm[(size_t)(row0 + r) * 256 + c] = v;
                *(__nv_bfloat16*)(sm + A_OFF + r * 512 + ((c * 2) ^ ((r & 7) << 4))) =
                    __float2bfloat16(v);
            }
            __syncwarp();
        }
    }
    __syncthreads();   // A ready; staging region free for B

    // ---- B chunk 0 via cp.async ----
    const char* esrc = (const char*)g_ebf;
    #pragma unroll
    for (int i = 0; i < 8; i++) {
        int f = tid + i * 512, r = f >> 5, kb16 = f & 31;
        cp16(smb + B_OFF + r * 512 + ((kb16 * 16) ^ ((r & 7) << 4)),
             esrc + (size_t)r * 512 + kb16 * 16);
    }
    CP_COMMIT();

    const unsigned c16 = ((l >> 4) & 1) * 16;
    unsigned aBase[2], xA[2];
    #pragma unroll
    for (int mf = 0; mf < 2; mf++) {
        int r = wm * 32 + mf * 16 + (l & 15);
        aBase[mf] = smb + A_OFF + r * 512;
        xA[mf] = c16 ^ ((r & 7) << 4);
    }
    unsigned bRow[2], xB[2];
    #pragma unroll
    for (int nfp = 0; nfp < 2; nfp++) {
        int r = wn * 32 + nfp * 16 + ((l >> 3) & 1) * 8 + (l & 7);
        bRow[nfp] = r * 512;
        xB[nfp] = c16 ^ ((r & 7) << 4);
    }

    for (int t = 0; t < 8; t++) {
        if (t < 7) {
            const char* src = esrc + (size_t)(t + 1) * 128 * 512;
            unsigned dstb = smb + B_OFF + ((t + 1) & 1) * 65536;
            #pragma unroll
            for (int i = 0; i < 8; i++) {
                int f = tid + i * 512, r = f >> 5, kb16 = f & 31;
                cp16(dstb + r * 512 + ((kb16 * 16) ^ ((r & 7) << 4)),
                     src + (size_t)r * 512 + kb16 * 16);
            }
            CP_COMMIT();
            CP_WAIT(1);
        } else {
            CP_WAIT(0);
        }
        __syncthreads();

        float acc[2][4][4];
        #pragma unroll
        for (int mf = 0; mf < 2; mf++)
            #pragma unroll
            for (int nf = 0; nf < 4; nf++)
                #pragma unroll
                for (int q = 0; q < 4; q++) acc[mf][nf][q] = 0.f;

        unsigned bB = smb + B_OFF + (t & 1) * 65536;

        // ---- mainloop with fragment double-buffering (LDSM overlaps MMA) ----
        unsigned afr[2][2][4], bfr[2][8];
        #pragma unroll
        for (int mf = 0; mf < 2; mf++)
            ldsm4(afr[0][mf][0], afr[0][mf][1], afr[0][mf][2], afr[0][mf][3],
                  aBase[mf] + (0 ^ xA[mf]));
        #pragma unroll
        for (int nfp = 0; nfp < 2; nfp++) {
            unsigned q0, q1, q2, q3;
            ldsm4(q0, q1, q2, q3, bB + bRow[nfp] + (0 ^ xB[nfp]));
            bfr[0][nfp * 4 + 0] = q0; bfr[0][nfp * 4 + 1] = q2;
            bfr[0][nfp * 4 + 2] = q1; bfr[0][nfp * 4 + 3] = q3;
        }
        #pragma unroll
        for (int ks = 0; ks < 16; ks++) {
            const int cur = ks & 1, nxt = cur ^ 1;
            if (ks < 15) {
                #pragma unroll
                for (int mf = 0; mf < 2; mf++)
                    ldsm4(afr[nxt][mf][0], afr[nxt][mf][1], afr[nxt][mf][2], afr[nxt][mf][3],
                          aBase[mf] + (((ks + 1) << 5) ^ xA[mf]));
                #pragma unroll
                for (int nfp = 0; nfp < 2; nfp++) {
                    unsigned q0, q1, q2, q3;
                    ldsm4(q0, q1, q2, q3, bB + bRow[nfp] + (((ks + 1) << 5) ^ xB[nfp]));
                    bfr[nxt][nfp * 4 + 0] = q0; bfr[nxt][nfp * 4 + 1] = q2;
                    bfr[nxt][nfp * 4 + 2] = q1; bfr[nxt][nfp * 4 + 3] = q3;
                }
            }
            #pragma unroll
            for (int mf = 0; mf < 2; mf++)
                #pragma unroll
                for (int nf = 0; nf < 4; nf++)
                    mma16816(acc[mf][nf], afr[cur][mf], bfr[cur][nf * 2], bfr[cur][nf * 2 + 1]);
        }

        // ---- epilogue: running-min push (score+idx recorded) ----
        #pragma unroll
        for (int mf = 0; mf < 2; mf++) {
            int r0l = wm * 32 + mf * 16 + (l >> 2);
            int r1l = r0l + 8;
            float mn0 = CUDART_INF_F, mn1 = CUDART_INF_F;
            #pragma unroll
            for (int nf = 0; nf < 4; nf++) {
                int gc = t * 128 + wn * 32 + nf * 8 + (l & 3) * 2;
                float se0 = se_sm[gc], se1 = se_sm[gc + 1];
                mn0 = fminf(mn0, fminf(fmaf(-2.f, acc[mf][nf][0], se0),
                                       fmaf(-2.f, acc[mf][nf][1], se1)));
                mn1 = fminf(mn1, fminf(fmaf(-2.f, acc[mf][nf][2], se0),
                                       fmaf(-2.f, acc[mf][nf][3], se1)));
            }
            mn0 = fminf(mn0, __shfl_xor_sync(0xffffffffu, mn0, 1));
            mn0 = fminf(mn0, __shfl_xor_sync(0xffffffffu, mn0, 2));
            mn1 = fminf(mn1, __shfl_xor_sync(0xffffffffu, mn1, 1));
            mn1 = fminf(mn1, __shfl_xor_sync(0xffffffffu, mn1, 2));
            if ((l & 3) == 0) {
                atomicMin(&sm_min[r0l], fmapu(mn0));
                atomicMin(&sm_min[r1l], fmapu(mn1));
            }
            __syncwarp();
            float thr0 = fminf(funmapu(((volatile unsigned*)sm_min)[r0l]), mn0) + MARGIN;
            float thr1 = fminf(funmapu(((volatile unsigned*)sm_min)[r1l]), mn1) + MARGIN;
            #pragma unroll
            for (int nf = 0; nf < 4; nf++) {
                int gc = t * 128 + wn * 32 + nf * 8 + (l & 3) * 2;
                float se0 = se_sm[gc], se1 = se_sm[gc + 1];
                float s00 = fmaf(-2.f, acc[mf][nf][0], se0);
                float s01 = fmaf(-2.f, acc[mf][nf][1], se1);
                float s10 = fmaf(-2.f, acc[mf][nf][2], se0);
                float s11 = fmaf(-2.f, acc[mf][nf][3], se1);
                if (s00 <= thr0) { int p = atomicAdd(&sm_cnt[r0l], 1); if (p < CAP) { sm_lh[r0l * CAP + p] = __float2half_rn(s00); sm_li[r0l * CAP + p] = (unsigned short)gc; } }
                if (s01 <= thr0) { int p = atomicAdd(&sm_cnt[r0l], 1); if (p < CAP) { sm_lh[r0l * CAP + p] = __float2half_rn(s01); sm_li[r0l * CAP + p] = (unsigned short)(gc + 1); } }
                if (s10 <= thr1) { int p = atomicAdd(&sm_cnt[r1l], 1); if (p < CAP) { sm_lh[r1l * CAP + p] = __float2half_rn(s10); sm_li[r1l * CAP + p] = (unsigned short)gc; } }
                if (s11 <= thr1) { int p = atomicAdd(&sm_cnt[r1l], 1); if (p < CAP) { sm_lh[r1l * CAP + p] = __float2half_rn(s11); sm_li[r1l * CAP + p] = (unsigned short)(gc + 1); } }
            }
        }
        __syncthreads();
    }

    // ================= fused exact-rescore tail =================
    unsigned long long* res = (unsigned long long*)(sm + RES_OFF);
    float* szv = (float*)(sm + SZV_OFF);
    int* offs = (int*)(sm + OFS_OFF);
    unsigned* wl = (unsigned*)(sm + WL_OFF);

    if (tid < 128) res[tid] = 0xFFFFFFFFFFFFFFFFull;

    // per-row sz from g_zrm (L2-hot, this CTA wrote it). R1-exact order (verbatim R5 tail).
    #pragma unroll
    for (int pass = 0; pass < 2; pass++) {
        int r = w * 8 + pass * 4 + (l >> 3);
        int y = l & 7;
        const float* zp = g_zrm + (size_t)(row0 + r) * CDIM;
        float p = 0.f;
        #pragma unroll 8
        for (int i = 0; i < 32; i++) {
            float v = zp[y + 8 * i];
            p = __fadd_rn(p, __fmul_rn(v, v));
        }
        int base = l & 24;
        float tt = __shfl_sync(0xffffffffu, p, base);
        #pragma unroll
        for (int yy = 1; yy < 8; yy++)
            tt = __fadd_rn(tt, __shfl_sync(0xffffffffu, p, base + yy));
        if (y == 0) szv[r] = tt;
    }

    // filter lists vs FINAL min, compact in place (warp per 8 rows)
    #pragma unroll 1
    for (int rr = 0; rr < 8; rr++) {
        int r = w * 8 + rr;
        int cntp = sm_cnt[r];
        if (cntp > CAP) { if (l == 0) sm_cnt[r] = -1; continue; }
        float thr = funmapu(sm_min[r]) + (MARGIN + 2.5e-4f);   // slack: fp16 rounding
        // cntp <= 48: read both batches into regs, then compact-write (no RAW hazard)
        bool k0 = false, k1 = false;
        unsigned short i0 = 0, i1 = 0;
        if (l < cntp)      { k0 = (__half2float(sm_lh[r * CAP + l]) <= thr);      i0 = sm_li[r * CAP + l]; }
        if (32 + l < cntp) { k1 = (__half2float(sm_lh[r * CAP + 32 + l]) <= thr); i1 = sm_li[r * CAP + 32 + l]; }
        unsigned m0 = __ballot_sync(0xffffffffu, k0);
        unsigned m1 = __ballot_sync(0xffffffffu, k1);
        if (k0) sm_li[r * CAP + __popc(m0 & ((1u << l) - 1))] = i0;
        if (k1) sm_li[r * CAP + __popc(m0) + __popc(m1 & ((1u << l) - 1))] = i1;
        if (l == 0) sm_cnt[r] = __popc(m0) + __popc(m1);
    }
    __syncthreads();

    // exclusive scan of counts -> worklist offsets (thread 0; 128 iters, cheap)
    if (tid == 0) {
        int acc0 = 0;
        for (int r = 0; r < 128; r++) {
            offs[r] = acc0;
            int c = sm_cnt[r];
            acc0 += (c > 0) ? c : 0;
        }
        offs[128] = acc0;
    }
    __syncthreads();

    // build worklist (warp per 8 rows)
    #pragma unroll 1
    for (int rr = 0; rr < 8; rr++) {
        int r = w * 8 + rr;
        int c = sm_cnt[r];
        for (int i = l; i < c; i += 32)
            wl[offs[r] + i] = ((unsigned)r << 16) | sm_li[r * CAP + i];
    }
    __syncthreads();

    // one exact dot per thread (R1-exact chain; z row L2-hot, emb L2-resident)
    int T = offs[128];
    for (int e = tid; e < T; e += 512) {
        unsigned ent = wl[e];
        int r = ent >> 16, j = ent & 0xffff;
        const float4* zp4 = (const float4*)(g_zrm + (size_t)(row0 + r) * CDIM);
        const float4* ep4 = (const float4*)(emb + (size_t)j * CDIM);
        float acc0 = 0.f;
        #pragma unroll 8
        for (int k4 = 0; k4 < 64; k4++) {
            float4 zv = zp4[k4];
            float4 ev = ep4[k4];
            acc0 = fmaf(zv.x, ev.x, acc0);
            acc0 = fmaf(zv.y, ev.y, acc0);
            acc0 = fmaf(zv.z, ev.z, acc0);
            acc0 = fmaf(zv.w, ev.w, acc0);
        }
        float d = fmaf(-2.f, acc0, __fadd_rn(szv[r], se_sm[j]));   // exact R1 rounding
        atomicMin(&res[r], ((unsigned long long)fmapu(d) << 32) | (unsigned)j);
    }

    // overflow rows (rare): full 1024-code exact sweep, all threads
    #pragma unroll 1
    for (int r = 0; r < 128; r++) {
        if (sm_cnt[r] >= 0) continue;
        const float4* zp4 = (const float4*)(g_zrm + (size_t)(row0 + r) * CDIM);
        for (int j = tid; j < NE; j += 512) {
            const float4* ep4 = (const float4*)(emb + (size_t)j * CDIM);
            float acc0 = 0.f;
            #pragma unroll 8
            for (int k4 = 0; k4 < 64; k4++) {
                float4 zv = zp4[k4];
                float4 ev = ep4[k4];
                acc0 = fmaf(zv.x, ev.x, acc0);
                acc0 = fmaf(zv.y, ev.y, acc0);
                acc0 = fmaf(zv.z, ev.z, acc0);
                acc0 = fmaf(zv.w, ev.w, acc0);
            }
            float d = fmaf(-2.f, acc0, __fadd_rn(szv[r], se_sm[j]));
            atomicMin(&res[r], ((unsigned long long)fmapu(d) << 32) | (unsigned)j);
        }
    }
    __syncthreads();

    // output + deterministic per-CTA loss partial
    if (tid < 128) out[row0 + tid] = (float)(unsigned)(res[tid] & 0xffffffffu);
    if (w == 0) {
        double s = 0.0;
        #pragma unroll
        for (int q = 0; q < 4; q++)
            s += (double)funmapu((unsigned)(res[l + q * 32] >> 32));
        #pragma unroll
        for (int off = 16; off; off >>= 1)
            s += __shfl_down_sync(0xffffffffu, s, off);
        if (l == 0) g_partial[blockIdx.x] = s;
    }
}

// ================= loss finalize =================
__global__ void loss2_kernel(float* __restrict__ out, int out_size) {
    __shared__ double s[256];
    int t = threadIdx.x;
    s[t] = g_partial[t];
    __syncthreads();
    for (int off = 128; off; off >>= 1) {
        if (t < off) s[t] += s[t + off];
        __syncthreads();
    }
    if (t == 0 && out_size > NROW) {
        float m = (float)(s[0] / (double)((size_t)NROW * CDIM));
        out[NROW] = m + 0.25f * m;
    }
}

extern "C" void kernel_launch(void* const* d_in, const int* in_sizes, int n_in,
                              void* d_out, int out_size) {
    const float* z   = (const float*)d_in[0];   // (32,256,32,32) fp32
    const float* emb = (const float*)d_in[1];   // (1024,256)     fp32
    float* out = (float*)d_out;

    eprep_kernel<<<1024, 256>>>(emb);
    se_kernel<<<1024, 64>>>(emb);
    pinit_kernel<<<1, 256>>>();                 // spacer: gemm lands in profiled slot #4

    static int smem_set = 0;
    if (!smem_set) {
        cudaFuncSetAttribute(gemm_kernel, cudaFuncAttributeMaxDynamicSharedMemorySize, SMEM_T);
        smem_set = 1;
    }
    gemm_kernel<<<256, 512, SMEM_T>>>(z, emb, out);

    loss2_kernel<<<1, 256>>>(out, out_size);
}

// round 12
// speedup vs baseline: 3.4599x; 1.2833x over previous
#include <cuda_runtime.h>
#include <cuda_bf16.h>
#include <cuda_fp16.h>
#include <math_constants.h>

#define NROW 32768
#define CDIM 256
#define NE   1024
#define MARGIN 4e-3f
#define CAP  48

// ---- static device scratch (allocation-free rule) ----
__device__ float          g_zrm[(size_t)NROW * CDIM];   // z row-major [n][c] fp32 (written by gemm)
__device__ __nv_bfloat16  g_ebf[(size_t)NE * CDIM];     // bf16(emb) [j][k]
__device__ float          g_se[NE];
__device__ int            g_cnt[NROW];
__device__ float          g_amin[NROW];
__device__ unsigned       g_list[(size_t)NROW * CAP];   // (fp16score<<16)|code
__device__ double         g_partial[256];

// ================= PTX helpers (baseline sm_80 ISA only) =================
__device__ __forceinline__ unsigned smem_u32(const void* p) {
    unsigned a;
    asm("{ .reg .u64 t; cvta.to.shared.u64 t, %1; cvt.u32.u64 %0, t; }" : "=r"(a) : "l"(p));
    return a;
}
__device__ __forceinline__ void cp16(unsigned dst, const void* src) {
    asm volatile("cp.async.cg.shared.global [%0], [%1], 16;" :: "r"(dst), "l"(src));
}
#define CP_COMMIT() asm volatile("cp.async.commit_group;" ::: "memory")
#define CP_WAIT(n)  asm volatile("cp.async.wait_group %0;" :: "n"(n) : "memory")

__device__ __forceinline__ void ldsm4(unsigned& r0, unsigned& r1, unsigned& r2, unsigned& r3,
                                      unsigned addr) {
    asm volatile("ldmatrix.sync.aligned.m8n8.x4.shared.b16 {%0,%1,%2,%3}, [%4];"
        : "=r"(r0), "=r"(r1), "=r"(r2), "=r"(r3) : "r"(addr));
}
__device__ __forceinline__ void mma16816(float* c, const unsigned* a, unsigned b0, unsigned b1) {
    asm volatile("mma.sync.aligned.m16n8k16.row.col.f32.bf16.bf16.f32 "
        "{%0,%1,%2,%3}, {%4,%5,%6,%7}, {%8,%9}, {%0,%1,%2,%3};"
        : "+f"(c[0]), "+f"(c[1]), "+f"(c[2]), "+f"(c[3])
        : "r"(a[0]), "r"(a[1]), "r"(a[2]), "r"(a[3]), "r"(b0), "r"(b1));
}
__device__ __forceinline__ unsigned fmapu(float f) {
    unsigned b = __float_as_uint(f);
    return (b & 0x80000000u) ? ~b : (b | 0x80000000u);
}
__device__ __forceinline__ float funmapu(unsigned u) {
    return (u & 0x80000000u) ? __uint_as_float(u & 0x7fffffffu) : __uint_as_float(~u);
}

// ================= prep kernels =================
__global__ void eprep_kernel(const float* __restrict__ e) {
    int i = blockIdx.x * 256 + threadIdx.x;
    g_ebf[i] = __float2bfloat16(e[i]);
}

__global__ void se_kernel(const float* __restrict__ e) {
    int j = blockIdx.x;
    float4 v = *(const float4*)&e[j * 256 + threadIdx.x * 4];
    float s = __fadd_rn(__fadd_rn(__fmul_rn(v.x,v.x), __fmul_rn(v.y,v.y)),
                        __fadd_rn(__fmul_rn(v.z,v.z), __fmul_rn(v.w,v.w)));
    for (int off = 16; off; off >>= 1) s += __shfl_down_sync(0xffffffffu, s, off);
    __shared__ float r2[2];
    if ((threadIdx.x & 31) == 0) r2[threadIdx.x >> 5] = s;
    __syncthreads();
    if (threadIdx.x == 0) g_se[j] = __fadd_rn(r2[0], r2[1]);
}

// ================= HMMA scoring + online shortlist (lean tail: dump only) =================
// smem: se 4KB | A 64KB | B 2x64KB (stage reuse) | min 512B | cnt 512B | u32 lists 24KB
#define SE_OFF   0
#define A_OFF    4096
#define B_OFF    (4096 + 65536)
#define MIN_OFF  (B_OFF + 131072)          // 200704
#define CNT_OFF  (MIN_OFF + 512)
#define LIST_OFF (CNT_OFF + 512)
#define SMEM_T   (LIST_OFF + 128 * CAP * 4)  // 226304

__global__ void __launch_bounds__(512) gemm_kernel(const float* __restrict__ z) {
    extern __shared__ char sm[];
    unsigned smb = smem_u32(sm);
    const int tid = threadIdx.x, l = tid & 31, w = tid >> 5;
    const int wm = w & 3, wn = w >> 2;           // 4x4 warp grid, 32x32 tiles
    const int row0 = blockIdx.x * 128;
    float* se_sm = (float*)(sm + SE_OFF);
    unsigned* sm_min = (unsigned*)(sm + MIN_OFF);
    int* sm_cnt = (int*)(sm + CNT_OFF);
    unsigned* sm_ul = (unsigned*)(sm + LIST_OFF);

    if (tid < 256) ((float4*)se_sm)[tid] = ((const float4*)g_se)[tid];
    if (tid < 128) { sm_min[tid] = 0xFFFFFFFFu; sm_cnt[tid] = 0; }

    // ---- phase 1: z slice from ORIGINAL layout -> zrm fp32 + bf16 A tile ----
    {
        const int b = row0 >> 10, hw0 = row0 & 1023;
        float* stg = (float*)(sm + B_OFF) + w * (36 * 32);
        #pragma unroll
        for (int tt = 0; tt < 2; tt++) {
            int ti = w * 2 + tt;
            int ci = ti >> 2, hi = ti & 3;
            #pragma unroll
            for (int i = 0; i < 8; i++) {
                int cl = i * 4 + (l >> 3);
                float4 v = *(const float4*)&z[((size_t)b << 18) + (size_t)(ci * 32 + cl) * 1024
                                              + hw0 + hi * 32 + (l & 7) * 4];
                *(float4*)&stg[cl * 36 + (l & 7) * 4] = v;
            }
            __syncwarp();
            int c = ci * 32 + l;
            #pragma unroll
            for (int rr = 0; rr < 32; rr++) {
                float v = stg[l * 36 + rr];
                int r = hi * 32 + rr;
                g_zrm[(size_t)(row0 + r) * 256 + c] = v;
                *(__nv_bfloat16*)(sm + A_OFF + r * 512 + ((c * 2) ^ ((r & 7) << 4))) =
                    __float2bfloat16(v);
            }
            __syncwarp();
        }
    }
    __syncthreads();

    // ---- B chunk 0 via cp.async ----
    const char* esrc = (const char*)g_ebf;
    #pragma unroll
    for (int i = 0; i < 8; i++) {
        int f = tid + i * 512, r = f >> 5, kb16 = f & 31;
        cp16(smb + B_OFF + r * 512 + ((kb16 * 16) ^ ((r & 7) << 4)),
             esrc + (size_t)r * 512 + kb16 * 16);
    }
    CP_COMMIT();

    const unsigned c16 = ((l >> 4) & 1) * 16;
    unsigned aBase[2], xA[2];
    #pragma unroll
    for (int mf = 0; mf < 2; mf++) {
        int r = wm * 32 + mf * 16 + (l & 15);
        aBase[mf] = smb + A_OFF + r * 512;
        xA[mf] = c16 ^ ((r & 7) << 4);
    }
    unsigned bRow[2], xB[2];
    #pragma unroll
    for (int nfp = 0; nfp < 2; nfp++) {
        int r = wn * 32 + nfp * 16 + ((l >> 3) & 1) * 8 + (l & 7);
        bRow[nfp] = r * 512;
        xB[nfp] = c16 ^ ((r & 7) << 4);
    }

    for (int t = 0; t < 8; t++) {
        if (t < 7) {
            const char* src = esrc + (size_t)(t + 1) * 128 * 512;
            unsigned dstb = smb + B_OFF + ((t + 1) & 1) * 65536;
            #pragma unroll
            for (int i = 0; i < 8; i++) {
                int f = tid + i * 512, r = f >> 5, kb16 = f & 31;
                cp16(dstb + r * 512 + ((kb16 * 16) ^ ((r & 7) << 4)),
                     src + (size_t)r * 512 + kb16 * 16);
            }
            CP_COMMIT();
            CP_WAIT(1);
        } else {
            CP_WAIT(0);
        }
        __syncthreads();

        float acc[2][4][4];
        #pragma unroll
        for (int mf = 0; mf < 2; mf++)
            #pragma unroll
            for (int nf = 0; nf < 4; nf++)
                #pragma unroll
                for (int q = 0; q < 4; q++) acc[mf][nf][q] = 0.f;

        unsigned bB = smb + B_OFF + (t & 1) * 65536;

        unsigned afr[2][2][4], bfr[2][8];
        #pragma unroll
        for (int mf = 0; mf < 2; mf++)
            ldsm4(afr[0][mf][0], afr[0][mf][1], afr[0][mf][2], afr[0][mf][3],
                  aBase[mf] + (0 ^ xA[mf]));
        #pragma unroll
        for (int nfp = 0; nfp < 2; nfp++) {
            unsigned q0, q1, q2, q3;
            ldsm4(q0, q1, q2, q3, bB + bRow[nfp] + (0 ^ xB[nfp]));
            bfr[0][nfp * 4 + 0] = q0; bfr[0][nfp * 4 + 1] = q2;
            bfr[0][nfp * 4 + 2] = q1; bfr[0][nfp * 4 + 3] = q3;
        }
        #pragma unroll
        for (int ks = 0; ks < 16; ks++) {
            const int cur = ks & 1, nxt = cur ^ 1;
            if (ks < 15) {
                #pragma unroll
                for (int mf = 0; mf < 2; mf++)
                    ldsm4(afr[nxt][mf][0], afr[nxt][mf][1], afr[nxt][mf][2], afr[nxt][mf][3],
                          aBase[mf] + (((ks + 1) << 5) ^ xA[mf]));
                #pragma unroll
                for (int nfp = 0; nfp < 2; nfp++) {
                    unsigned q0, q1, q2, q3;
                    ldsm4(q0, q1, q2, q3, bB + bRow[nfp] + (((ks + 1) << 5) ^ xB[nfp]));
                    bfr[nxt][nfp * 4 + 0] = q0; bfr[nxt][nfp * 4 + 1] = q2;
                    bfr[nxt][nfp * 4 + 2] = q1; bfr[nxt][nfp * 4 + 3] = q3;
                }
            }
            #pragma unroll
            for (int mf = 0; mf < 2; mf++)
                #pragma unroll
                for (int nf = 0; nf < 4; nf++)
                    mma16816(acc[mf][nf], afr[cur][mf], bfr[cur][nf * 2], bfr[cur][nf * 2 + 1]);
        }

        // ---- epilogue: running-min push, packed u32 (fp16score<<16|code) ----
        #pragma unroll
        for (int mf = 0; mf < 2; mf++) {
            int r0l = wm * 32 + mf * 16 + (l >> 2);
            int r1l = r0l + 8;
            float mn0 = CUDART_INF_F, mn1 = CUDART_INF_F;
            #pragma unroll
            for (int nf = 0; nf < 4; nf++) {
                int gc = t * 128 + wn * 32 + nf * 8 + (l & 3) * 2;
                float se0 = se_sm[gc], se1 = se_sm[gc + 1];
                mn0 = fminf(mn0, fminf(fmaf(-2.f, acc[mf][nf][0], se0),
                                       fmaf(-2.f, acc[mf][nf][1], se1)));
                mn1 = fminf(mn1, fminf(fmaf(-2.f, acc[mf][nf][2], se0),
                                       fmaf(-2.f, acc[mf][nf][3], se1)));
            }
            mn0 = fminf(mn0, __shfl_xor_sync(0xffffffffu, mn0, 1));
            mn0 = fminf(mn0, __shfl_xor_sync(0xffffffffu, mn0, 2));
            mn1 = fminf(mn1, __shfl_xor_sync(0xffffffffu, mn1, 1));
            mn1 = fminf(mn1, __shfl_xor_sync(0xffffffffu, mn1, 2));
            if ((l & 3) == 0) {
                atomicMin(&sm_min[r0l], fmapu(mn0));
                atomicMin(&sm_min[r1l], fmapu(mn1));
            }
            __syncwarp();
            float thr0 = fminf(funmapu(((volatile unsigned*)sm_min)[r0l]), mn0) + MARGIN;
            float thr1 = fminf(funmapu(((volatile unsigned*)sm_min)[r1l]), mn1) + MARGIN;
            #pragma unroll
            for (int nf = 0; nf < 4; nf++) {
                int gc = t * 128 + wn * 32 + nf * 8 + (l & 3) * 2;
                float se0 = se_sm[gc], se1 = se_sm[gc + 1];
                float s00 = fmaf(-2.f, acc[mf][nf][0], se0);
                float s01 = fmaf(-2.f, acc[mf][nf][1], se1);
                float s10 = fmaf(-2.f, acc[mf][nf][2], se0);
                float s11 = fmaf(-2.f, acc[mf][nf][3], se1);
                if (s00 <= thr0) { int p = atomicAdd(&sm_cnt[r0l], 1); if (p < CAP) sm_ul[r0l * CAP + p] = ((unsigned)__half_as_ushort(__float2half_rn(s00)) << 16) | (unsigned)gc; }
                if (s01 <= thr0) { int p = atomicAdd(&sm_cnt[r0l], 1); if (p < CAP) sm_ul[r0l * CAP + p] = ((unsigned)__half_as_ushort(__float2half_rn(s01)) << 16) | (unsigned)(gc + 1); }
                if (s10 <= thr1) { int p = atomicAdd(&sm_cnt[r1l], 1); if (p < CAP) sm_ul[r1l * CAP + p] = ((unsigned)__half_as_ushort(__float2half_rn(s10)) << 16) | (unsigned)gc; }
                if (s11 <= thr1) { int p = atomicAdd(&sm_cnt[r1l], 1); if (p < CAP) sm_ul[r1l * CAP + p] = ((unsigned)__half_as_ushort(__float2half_rn(s11)) << 16) | (unsigned)(gc + 1); }
            }
        }
        __syncthreads();
    }

    // ---- lean dump: counts, final mins, used list entries ----
    #pragma unroll 1
    for (int rr = 0; rr < 8; rr++) {
        int r = w * 8 + rr, row = row0 + r;
        int cntp = sm_cnt[r];
        if (l == 0) { g_cnt[row] = cntp; g_amin[row] = funmapu(sm_min[r]); }
        int m2 = min(cntp, CAP);
        for (int i = l; i < m2; i += 32)
            g_list[(size_t)row * CAP + i] = sm_ul[r * CAP + i];
    }
}

// ================= worklist rescore: 256 CTAs, warp owns 8 rows, 8-lane dot split =================
__global__ void __launch_bounds__(512) rescore2_kernel(const float* __restrict__ emb,
                                                       float* __restrict__ out) {
    __shared__ unsigned wbuf[16][CAP];
    __shared__ double ws[16];
    const int tid = threadIdx.x, l = tid & 31, w = tid >> 5;
    const int row0 = blockIdx.x * 128;
    const int g = l >> 3, lg = l & 7;   // 4 candidate groups x 8 lanes

    double wsum = 0.0;
    #pragma unroll 1
    for (int rr = 0; rr < 8; rr++) {
        int row = row0 + w * 8 + rr;
        const float4* zp4 = (const float4*)(g_zrm + (size_t)row * CDIM);

        // sz (order-free; cancels row-wise in argmin, error ~1e-4 on ~256 irrelevant)
        float4 a4 = zp4[l * 2], b4 = zp4[l * 2 + 1];
        float ss = a4.x * a4.x;
        ss = fmaf(a4.y, a4.y, ss); ss = fmaf(a4.z, a4.z, ss); ss = fmaf(a4.w, a4.w, ss);
        ss = fmaf(b4.x, b4.x, ss); ss = fmaf(b4.y, b4.y, ss);
        ss = fmaf(b4.z, b4.z, ss); ss = fmaf(b4.w, b4.w, ss);
        #pragma unroll
        for (int off = 16; off; off >>= 1) ss += __shfl_xor_sync(0xffffffffu, ss, off);
        float sz = ss;

        int cnt = g_cnt[row];
        float thr = g_amin[row] + (MARGIN + 2.5e-4f);
        bool swept = (cnt > CAP);
        int total;
        if (!swept) {
            bool k0 = false, k1 = false; unsigned e0 = 0, e1 = 0;
            if (l < cnt)      { e0 = g_list[(size_t)row * CAP + l];      k0 = __half2float(__ushort_as_half((unsigned short)(e0 >> 16))) <= thr; }
            if (32 + l < cnt) { e1 = g_list[(size_t)row * CAP + 32 + l]; k1 = __half2float(__ushort_as_half((unsigned short)(e1 >> 16))) <= thr; }
            unsigned m0 = __ballot_sync(0xffffffffu, k0);
            unsigned m1 = __ballot_sync(0xffffffffu, k1);
            if (k0) wbuf[w][__popc(m0 & ((1u << l) - 1))] = e0;
            if (k1) wbuf[w][__popc(m0) + __popc(m1 & ((1u << l) - 1))] = e1;
            total = __popc(m0) + __popc(m1);
        } else {
            total = NE;
        }
        __syncwarp();

        float bd = CUDART_INF_F; int bj = 0x7fffffff;
        for (int c0 = 0; c0 < total; c0 += 4) {
            int ci = c0 + g;
            bool valid = ci < total;
            int j = 0;
            if (valid) j = swept ? ci : (int)(wbuf[w][ci] & 0xffffu);
            float dot = 0.f;
            float sej = 0.f;
            if (valid) {
                const float4* ep4 = (const float4*)(emb + (size_t)j * CDIM);
                sej = g_se[j];
                #pragma unroll
                for (int q = 0; q < 8; q++) {
                    float4 zv = zp4[lg + q * 8];
                    float4 ev = ep4[lg + q * 8];
                    dot = fmaf(zv.x, ev.x, dot);
                    dot = fmaf(zv.y, ev.y, dot);
                    dot = fmaf(zv.z, ev.z, dot);
                    dot = fmaf(zv.w, ev.w, dot);
                }
            }
            dot += __shfl_xor_sync(0xffffffffu, dot, 4);
            dot += __shfl_xor_sync(0xffffffffu, dot, 2);
            dot += __shfl_xor_sync(0xffffffffu, dot, 1);
            float d = valid ? fmaf(-2.f, dot, __fadd_rn(sz, sej)) : CUDART_INF_F;
            int jv = valid ? j : 0x7fffffff;
            // cross-group min (tie -> lower code)
            #pragma unroll
            for (int off = 8; off <= 16; off <<= 1) {
                float od = __shfl_xor_sync(0xffffffffu, d, off);
                int   oj = __shfl_xor_sync(0xffffffffu, jv, off);
                if (od < d || (od == d && oj < jv)) { d = od; jv = oj; }
            }
            if (d < bd || (d == bd && jv < bj)) { bd = d; bj = jv; }
        }
        if (l == 0) { out[row] = (float)bj; wsum += (double)bd; }
    }
    if (l == 0) ws[w] = wsum;
    __syncthreads();
    if (tid == 0) {
        double s = 0.0;
        #pragma unroll
        for (int i = 0; i < 16; i++) s += ws[i];
        g_partial[blockIdx.x] = s;
    }
}

// ================= loss finalize =================
__global__ void loss2_kernel(float* __restrict__ out, int out_size) {
    __shared__ double s[256];
    int t = threadIdx.x;
    s[t] = g_partial[t];
    __syncthreads();
    for (int off = 128; off; off >>= 1) {
        if (t < off) s[t] += s[t + off];
        __syncthreads();
    }
    if (t == 0 && out_size > NROW) {
        float m = (float)(s[0] / (double)((size_t)NROW * CDIM));
        out[NROW] = m + 0.25f * m;
    }
}

extern "C" void kernel_launch(void* const* d_in, const int* in_sizes, int n_in,
                              void* d_out, int out_size) {
    const float* z   = (const float*)d_in[0];   // (32,256,32,32) fp32
    const float* emb = (const float*)d_in[1];   // (1024,256)     fp32
    float* out = (float*)d_out;

    eprep_kernel<<<1024, 256>>>(emb);
    se_kernel<<<1024, 64>>>(emb);

    static int smem_set = 0;
    if (!smem_set) {
        cudaFuncSetAttribute(gemm_kernel, cudaFuncAttributeMaxDynamicSharedMemorySize, SMEM_T);
        smem_set = 1;
    }
    gemm_kernel<<<256, 512, SMEM_T>>>(z);        // slot 3

    rescore2_kernel<<<256, 512>>>(emb, out);     // slot 4 -> profiled this round
    loss2_kernel<<<1, 256>>>(out, out_size);
}